// round 3
// baseline (speedup 1.0000x reference)
#include <cuda_runtime.h>

// ---------------- problem constants ----------------
#define NMAX 100000
#define H    128

// ---------------- device scratch (no allocs allowed) ----------------
__device__ float g_dinv[NMAX];                       // deg -> rsqrt(deg)
__device__ float g_hW [(size_t)NMAX * H];            // h @ W (pre-aggregation)
__device__ float g_agg[(size_t)NMAX * H];            // aggregated messages
__device__ float g_cat[(size_t)NMAX * 3 * H];        // JK concat buffer, ld=384

// ---------------- degree / norm ----------------
__global__ void k_deg_init(float* __restrict__ dinv, int N) {
    int i = blockIdx.x * blockDim.x + threadIdx.x;
    if (i < N) dinv[i] = 1.0f;
}

__global__ void k_deg_count(float* __restrict__ dinv,
                            const int* __restrict__ ei, int E) {
    int e = blockIdx.x * blockDim.x + threadIdx.x;
    if (e < E) atomicAdd(&dinv[ei[E + e]], 1.0f);
}

__global__ void k_deg_fin(float* __restrict__ dinv, int N) {
    int i = blockIdx.x * blockDim.x + threadIdx.x;
    if (i < N) dinv[i] = rsqrtf(dinv[i]);
}

// ---------------- conv GEMM: hW = X @ W ; agg = hW * dinv^2 ----------------
// X: [N, ldx] (reads 128 cols), W: [128,128] row-major.
// Block: 64 rows x 128 cols, 256 threads, each thread 8 rows x 4 cols.
__global__ void __launch_bounds__(256) k_conv_gemm(
    const float* __restrict__ X, int ldx,
    const float* __restrict__ W,
    const float* __restrict__ dinv,
    float* __restrict__ hW,
    float* __restrict__ agg, int N)
{
    __shared__ float Ws[64][128];   // 32 KB  (K-chunk x 128 cols)
    __shared__ float Xs[64][64];    // 16 KB  (64 rows x K-chunk)

    const int tid  = threadIdx.x;
    const int row0 = blockIdx.x * 64;
    const int tx   = tid & 31;   // -> col base tx*4
    const int ty   = tid >> 5;   // -> row base ty*8

    float acc[8][4];
#pragma unroll
    for (int r = 0; r < 8; r++)
#pragma unroll
        for (int c = 0; c < 4; c++) acc[r][c] = 0.f;

    for (int kc = 0; kc < 128; kc += 64) {
        __syncthreads();
        // load W rows [kc, kc+64): 64*128 floats = 2048 float4
#pragma unroll
        for (int i = tid; i < 2048; i += 256)
            ((float4*)Ws)[i] = ((const float4*)(W + (size_t)kc * 128))[i];
        // load X tile cols [kc, kc+64): 64*64 floats = 1024 float4
#pragma unroll
        for (int i = tid; i < 1024; i += 256) {
            int r = i >> 4, c4 = i & 15;
            int gr = row0 + r;
            float4 v = make_float4(0.f, 0.f, 0.f, 0.f);
            if (gr < N) v = *(const float4*)(X + (size_t)gr * ldx + kc + c4 * 4);
            ((float4*)&Xs[r][0])[c4] = v;
        }
        __syncthreads();

#pragma unroll
        for (int k = 0; k < 64; k += 4) {
            float4 wv[4];
#pragma unroll
            for (int kk = 0; kk < 4; kk++)
                wv[kk] = *(const float4*)&Ws[k + kk][tx * 4];
#pragma unroll
            for (int r = 0; r < 8; r++) {
                float4 xv = *(const float4*)&Xs[ty * 8 + r][k];
                acc[r][0] += xv.x * wv[0].x + xv.y * wv[1].x + xv.z * wv[2].x + xv.w * wv[3].x;
                acc[r][1] += xv.x * wv[0].y + xv.y * wv[1].y + xv.z * wv[2].y + xv.w * wv[3].y;
                acc[r][2] += xv.x * wv[0].z + xv.y * wv[1].z + xv.z * wv[2].z + xv.w * wv[3].z;
                acc[r][3] += xv.x * wv[0].w + xv.y * wv[1].w + xv.z * wv[2].w + xv.w * wv[3].w;
            }
        }
    }

    // epilogue: write hW and agg = hW * dinv^2 (self-loop term)
#pragma unroll
    for (int r = 0; r < 8; r++) {
        int gr = row0 + ty * 8 + r;
        if (gr < N) {
            float dv = dinv[gr];
            float sn = dv * dv;
            float4 a = make_float4(acc[r][0], acc[r][1], acc[r][2], acc[r][3]);
            *(float4*)(hW  + (size_t)gr * H + tx * 4) = a;
            float4 s = make_float4(a.x * sn, a.y * sn, a.z * sn, a.w * sn);
            *(float4*)(agg + (size_t)gr * H + tx * 4) = s;
        }
    }
}

// ---------------- edge scatter: agg[col] += hW[row] * dinv[row]*dinv[col] ----------------
// one warp per edge; lane handles 4 consecutive floats (float4 gather).
__global__ void __launch_bounds__(256) k_scatter(
    const int* __restrict__ ei,
    const float* __restrict__ dinv,
    const float* __restrict__ hW,
    float* __restrict__ agg, int E)
{
    int e = blockIdx.x * 8 + (threadIdx.x >> 5);
    if (e >= E) return;
    int lane = threadIdx.x & 31;
    int r = ei[e];
    int c = ei[E + e];
    float nrm = dinv[r] * dinv[c];
    float4 v = ((const float4*)(hW + (size_t)r * H))[lane];
    float* dst = agg + (size_t)c * H + lane * 4;
    atomicAdd(dst + 0, v.x * nrm);
    atomicAdd(dst + 1, v.y * nrm);
    atomicAdd(dst + 2, v.z * nrm);
    atomicAdd(dst + 3, v.w * nrm);
}

// ---------------- relu + bias -> cat slice ----------------
__global__ void k_relu_bias(const float* __restrict__ agg,
                            const float* __restrict__ b,
                            float* __restrict__ cat, int off4, int N)
{
    int idx = blockIdx.x * blockDim.x + threadIdx.x;  // float4 index over N*32
    if (idx >= N * 32) return;
    int row = idx >> 5, c4 = idx & 31;
    float4 v  = ((const float4*)agg)[idx];
    float4 bb = ((const float4*)b)[c4];
    v.x = fmaxf(v.x + bb.x, 0.f);
    v.y = fmaxf(v.y + bb.y, 0.f);
    v.z = fmaxf(v.z + bb.z, 0.f);
    v.w = fmaxf(v.w + bb.w, 0.f);
    ((float4*)cat)[(size_t)row * 96 + off4 + c4] = v;
}

// ---------------- final GEMM: out = cat[100K,384] @ Wlin[384,64] + blin ----------------
// Block: 64 rows x 64 cols, 256 threads, each thread 8 rows x 2 cols, K chunked by 64.
__global__ void __launch_bounds__(256) k_final_gemm(
    const float* __restrict__ cat,
    const float* __restrict__ W,     // [384,64] row-major
    const float* __restrict__ bias,  // [64]
    float* __restrict__ out, int N)
{
    __shared__ float Ws[64][64];    // 16 KB
    __shared__ float Xs[64][64];    // 16 KB

    const int tid  = threadIdx.x;
    const int row0 = blockIdx.x * 64;
    const int tx   = tid & 31;   // col base tx*2
    const int ty   = tid >> 5;   // row base ty*8

    float acc[8][2];
#pragma unroll
    for (int r = 0; r < 8; r++) { acc[r][0] = 0.f; acc[r][1] = 0.f; }

    for (int kc = 0; kc < 384; kc += 64) {
        __syncthreads();
#pragma unroll
        for (int i = tid; i < 1024; i += 256)   // 64*64/4
            ((float4*)Ws)[i] = ((const float4*)(W + (size_t)kc * 64))[i];
#pragma unroll
        for (int i = tid; i < 1024; i += 256) {
            int r = i >> 4, c4 = i & 15;
            int gr = row0 + r;
            float4 v = make_float4(0.f, 0.f, 0.f, 0.f);
            if (gr < N) v = *(const float4*)(cat + (size_t)gr * 384 + kc + c4 * 4);
            ((float4*)&Xs[r][0])[c4] = v;
        }
        __syncthreads();

#pragma unroll
        for (int k = 0; k < 64; k += 4) {
            float2 wv[4];
#pragma unroll
            for (int kk = 0; kk < 4; kk++)
                wv[kk] = *(const float2*)&Ws[k + kk][tx * 2];
#pragma unroll
            for (int r = 0; r < 8; r++) {
                float4 xv = *(const float4*)&Xs[ty * 8 + r][k];
                acc[r][0] += xv.x * wv[0].x + xv.y * wv[1].x + xv.z * wv[2].x + xv.w * wv[3].x;
                acc[r][1] += xv.x * wv[0].y + xv.y * wv[1].y + xv.z * wv[2].y + xv.w * wv[3].y;
            }
        }
    }

    float2 bb = *(const float2*)&bias[tx * 2];
#pragma unroll
    for (int r = 0; r < 8; r++) {
        int gr = row0 + ty * 8 + r;
        if (gr < N) {
            float2 o;
            o.x = acc[r][0] + bb.x;
            o.y = acc[r][1] + bb.y;
            *(float2*)(out + (size_t)gr * 64 + tx * 2) = o;
        }
    }
}

// ---------------- launch ----------------
extern "C" void kernel_launch(void* const* d_in, const int* in_sizes, int n_in,
                              void* d_out, int out_size)
{
    const float* x    = (const float*)d_in[0];
    const int*   ei   = (const int*)d_in[1];      // int32! (JAX x64 disabled)
    const float* W1   = (const float*)d_in[2];
    const float* b1   = (const float*)d_in[3];
    const float* W2   = (const float*)d_in[4];
    const float* b2   = (const float*)d_in[5];
    const float* W3   = (const float*)d_in[6];
    const float* b3   = (const float*)d_in[7];
    const float* Wlin = (const float*)d_in[8];
    const float* blin = (const float*)d_in[9];
    float* out = (float*)d_out;

    // Resolve device-global scratch addresses (host-legal, capture-legal).
    float *dinv, *hW, *agg, *cat;
    cudaGetSymbolAddress((void**)&dinv, g_dinv);
    cudaGetSymbolAddress((void**)&hW,   g_hW);
    cudaGetSymbolAddress((void**)&agg,  g_agg);
    cudaGetSymbolAddress((void**)&cat,  g_cat);

    const int N = in_sizes[0] / H;      // 100000
    const int E = in_sizes[1] / 2;      // 1600000

    const int nThreads = 256;
    const int gN    = (N + nThreads - 1) / nThreads;
    const int gE    = (E + nThreads - 1) / nThreads;
    const int gGemm = (N + 63) / 64;
    const int gScat = (E + 7) / 8;
    const int gRelu = (N * 32 + nThreads - 1) / nThreads;

    // degree / normalization
    k_deg_init <<<gN, nThreads>>>(dinv, N);
    k_deg_count<<<gE, nThreads>>>(dinv, ei, E);
    k_deg_fin  <<<gN, nThreads>>>(dinv, N);

    // layer 1: input = x (ld 128)
    k_conv_gemm<<<gGemm, nThreads>>>(x, H, W1, dinv, hW, agg, N);
    k_scatter  <<<gScat, nThreads>>>(ei, dinv, hW, agg, E);
    k_relu_bias<<<gRelu, nThreads>>>(agg, b1, cat, 0, N);

    // layer 2: input = cat slice 0 (ld 384)
    k_conv_gemm<<<gGemm, nThreads>>>(cat, 384, W2, dinv, hW, agg, N);
    k_scatter  <<<gScat, nThreads>>>(ei, dinv, hW, agg, E);
    k_relu_bias<<<gRelu, nThreads>>>(agg, b2, cat, 32, N);

    // layer 3: input = cat slice 1 (ld 384)
    k_conv_gemm<<<gGemm, nThreads>>>(cat + H, 384, W3, dinv, hW, agg, N);
    k_scatter  <<<gScat, nThreads>>>(ei, dinv, hW, agg, E);
    k_relu_bias<<<gRelu, nThreads>>>(agg, b3, cat, 64, N);

    // final: out = cat @ Wlin + blin
    k_final_gemm<<<gGemm, nThreads>>>(cat, Wlin, blin, out, N);
}

// round 4
// speedup vs baseline: 2.9203x; 2.9203x over previous
#include <cuda_runtime.h>

// ---------------- problem constants ----------------
#define NMAX 100000
#define EMAX 1600000
#define H    128
#define SCAN_CHUNK 512
#define NB_MAX 256   // >= ceil(NMAX/SCAN_CHUNK) = 196

// ---------------- device scratch (no allocs allowed) ----------------
__device__ float g_dinv[NMAX];
__device__ int   g_deg[NMAX];                 // in-degree histogram (excl. self-loop)
__device__ int   g_rowptr[NMAX + 1];          // CSR offsets by destination
__device__ int   g_cursor[NMAX];              // fill cursors
__device__ int   g_bsums[NB_MAX];             // scan block sums
__device__ int   g_csr_src[EMAX];             // source node per CSR slot
__device__ float g_csr_w[EMAX];               // dinv[src] per CSR slot
__device__ float g_hW [(size_t)NMAX * H];     // h @ W (pre-aggregation)
__device__ float g_cat[(size_t)NMAX * 3 * H]; // JK concat buffer, ld=384

// ---------------- CSR build ----------------
__global__ void k_zero_deg(int* __restrict__ deg, int N) {
    int i = blockIdx.x * blockDim.x + threadIdx.x;
    if (i < N) deg[i] = 0;
}

__global__ void k_hist(int* __restrict__ deg, const int* __restrict__ ei, int E) {
    int e = blockIdx.x * blockDim.x + threadIdx.x;
    if (e < E) atomicAdd(&deg[ei[E + e]], 1);
}

__global__ void k_dinv(float* __restrict__ dinv, const int* __restrict__ deg, int N) {
    int i = blockIdx.x * blockDim.x + threadIdx.x;
    if (i < N) dinv[i] = rsqrtf(1.0f + (float)deg[i]);   // +1 for self-loop
}

// scan stage 1: per-chunk sums
__global__ void __launch_bounds__(SCAN_CHUNK) k_scan1(
    const int* __restrict__ deg, int* __restrict__ bsums, int N)
{
    __shared__ int s[SCAN_CHUNK];
    int t = threadIdx.x;
    int i = blockIdx.x * SCAN_CHUNK + t;
    s[t] = (i < N) ? deg[i] : 0;
    __syncthreads();
    for (int off = SCAN_CHUNK / 2; off > 0; off >>= 1) {
        if (t < off) s[t] += s[t + off];
        __syncthreads();
    }
    if (t == 0) bsums[blockIdx.x] = s[0];
}

// scan stage 2: exclusive scan of block sums (single block), write rowptr[N]=total
__global__ void __launch_bounds__(NB_MAX) k_scan2(
    int* __restrict__ bsums, int* __restrict__ rowptr, int NB, int N)
{
    __shared__ int s[NB_MAX];
    int t = threadIdx.x;
    int v = (t < NB) ? bsums[t] : 0;
    s[t] = v;
    __syncthreads();
    for (int off = 1; off < NB_MAX; off <<= 1) {
        int x = (t >= off) ? s[t - off] : 0;
        __syncthreads();
        s[t] += x;
        __syncthreads();
    }
    if (t < NB) bsums[t] = s[t] - v;          // exclusive
    if (t == NB_MAX - 1) rowptr[N] = s[NB_MAX - 1];  // total = E
}

// scan stage 3: per-chunk exclusive scan + offset -> rowptr, cursor
__global__ void __launch_bounds__(SCAN_CHUNK) k_scan3(
    const int* __restrict__ deg, const int* __restrict__ bsums,
    int* __restrict__ rowptr, int* __restrict__ cursor, int N)
{
    __shared__ int s[SCAN_CHUNK];
    int t = threadIdx.x;
    int i = blockIdx.x * SCAN_CHUNK + t;
    int v = (i < N) ? deg[i] : 0;
    s[t] = v;
    __syncthreads();
    for (int off = 1; off < SCAN_CHUNK; off <<= 1) {
        int x = (t >= off) ? s[t - off] : 0;
        __syncthreads();
        s[t] += x;
        __syncthreads();
    }
    if (i < N) {
        int excl = s[t] - v + bsums[blockIdx.x];
        rowptr[i] = excl;
        cursor[i] = excl;
    }
}

__global__ void k_fill(const int* __restrict__ ei,
                       const float* __restrict__ dinv,
                       int* __restrict__ cursor,
                       int* __restrict__ csr_src,
                       float* __restrict__ csr_w, int E)
{
    int e = blockIdx.x * blockDim.x + threadIdx.x;
    if (e >= E) return;
    int r = ei[e];
    int c = ei[E + e];
    int pos = atomicAdd(&cursor[c], 1);
    csr_src[pos] = r;
    csr_w[pos]   = dinv[r];
}

// ---------------- conv GEMM: hW = X @ W ----------------
// X: [N, ldx] (reads 128 cols), W: [128,128] row-major.
// Block: 64 rows x 128 cols, 256 threads, each thread 8 rows x 4 cols.
__global__ void __launch_bounds__(256) k_conv_gemm(
    const float* __restrict__ X, int ldx,
    const float* __restrict__ W,
    float* __restrict__ hW, int N)
{
    __shared__ float Ws[64][128];   // 32 KB
    __shared__ float Xs[64][64];    // 16 KB

    const int tid  = threadIdx.x;
    const int row0 = blockIdx.x * 64;
    const int tx   = tid & 31;
    const int ty   = tid >> 5;

    float acc[8][4];
#pragma unroll
    for (int r = 0; r < 8; r++)
#pragma unroll
        for (int c = 0; c < 4; c++) acc[r][c] = 0.f;

    for (int kc = 0; kc < 128; kc += 64) {
        __syncthreads();
#pragma unroll
        for (int i = tid; i < 2048; i += 256)
            ((float4*)Ws)[i] = ((const float4*)(W + (size_t)kc * 128))[i];
#pragma unroll
        for (int i = tid; i < 1024; i += 256) {
            int r = i >> 4, c4 = i & 15;
            int gr = row0 + r;
            float4 v = make_float4(0.f, 0.f, 0.f, 0.f);
            if (gr < N) v = *(const float4*)(X + (size_t)gr * ldx + kc + c4 * 4);
            ((float4*)&Xs[r][0])[c4] = v;
        }
        __syncthreads();

#pragma unroll
        for (int k = 0; k < 64; k += 4) {
            float4 wv[4];
#pragma unroll
            for (int kk = 0; kk < 4; kk++)
                wv[kk] = *(const float4*)&Ws[k + kk][tx * 4];
#pragma unroll
            for (int r = 0; r < 8; r++) {
                float4 xv = *(const float4*)&Xs[ty * 8 + r][k];
                acc[r][0] += xv.x * wv[0].x + xv.y * wv[1].x + xv.z * wv[2].x + xv.w * wv[3].x;
                acc[r][1] += xv.x * wv[0].y + xv.y * wv[1].y + xv.z * wv[2].y + xv.w * wv[3].y;
                acc[r][2] += xv.x * wv[0].z + xv.y * wv[1].z + xv.z * wv[2].z + xv.w * wv[3].z;
                acc[r][3] += xv.x * wv[0].w + xv.y * wv[1].w + xv.z * wv[2].w + xv.w * wv[3].w;
            }
        }
    }

#pragma unroll
    for (int r = 0; r < 8; r++) {
        int gr = row0 + ty * 8 + r;
        if (gr < N)
            *(float4*)(hW + (size_t)gr * H + tx * 4) =
                make_float4(acc[r][0], acc[r][1], acc[r][2], acc[r][3]);
    }
}

// ---------------- fused aggregate + self-loop + bias + relu -> cat slice ----------------
// one warp per destination node; lane owns 4 consecutive floats.
__global__ void __launch_bounds__(256) k_aggregate(
    const int* __restrict__ rowptr,
    const int* __restrict__ csr_src,
    const float* __restrict__ csr_w,
    const float* __restrict__ dinv,
    const float* __restrict__ hW,
    const float* __restrict__ bias,
    float* __restrict__ cat, int off4, int N)
{
    int n = blockIdx.x * 8 + (threadIdx.x >> 5);
    if (n >= N) return;
    int lane = threadIdx.x & 31;

    float dv = dinv[n];
    float sn = dv * dv;
    float4 self = ((const float4*)(hW + (size_t)n * H))[lane];
    float4 acc = make_float4(self.x * sn, self.y * sn, self.z * sn, self.w * sn);

    int beg = rowptr[n], end = rowptr[n + 1];
    for (int i = beg; i < end; i++) {
        int   r = csr_src[i];
        float w = csr_w[i] * dv;
        float4 v = ((const float4*)(hW + (size_t)r * H))[lane];
        acc.x += v.x * w;
        acc.y += v.y * w;
        acc.z += v.z * w;
        acc.w += v.w * w;
    }

    float4 bb = ((const float4*)bias)[lane];
    acc.x = fmaxf(acc.x + bb.x, 0.f);
    acc.y = fmaxf(acc.y + bb.y, 0.f);
    acc.z = fmaxf(acc.z + bb.z, 0.f);
    acc.w = fmaxf(acc.w + bb.w, 0.f);
    ((float4*)cat)[(size_t)n * 96 + off4 + lane] = acc;
}

// ---------------- final GEMM: out = cat[100K,384] @ Wlin[384,64] + blin ----------------
__global__ void __launch_bounds__(256) k_final_gemm(
    const float* __restrict__ cat,
    const float* __restrict__ W,     // [384,64] row-major
    const float* __restrict__ bias,  // [64]
    float* __restrict__ out, int N)
{
    __shared__ float Ws[64][64];
    __shared__ float Xs[64][64];

    const int tid  = threadIdx.x;
    const int row0 = blockIdx.x * 64;
    const int tx   = tid & 31;
    const int ty   = tid >> 5;

    float acc[8][2];
#pragma unroll
    for (int r = 0; r < 8; r++) { acc[r][0] = 0.f; acc[r][1] = 0.f; }

    for (int kc = 0; kc < 384; kc += 64) {
        __syncthreads();
#pragma unroll
        for (int i = tid; i < 1024; i += 256)
            ((float4*)Ws)[i] = ((const float4*)(W + (size_t)kc * 64))[i];
#pragma unroll
        for (int i = tid; i < 1024; i += 256) {
            int r = i >> 4, c4 = i & 15;
            int gr = row0 + r;
            float4 v = make_float4(0.f, 0.f, 0.f, 0.f);
            if (gr < N) v = *(const float4*)(cat + (size_t)gr * 384 + kc + c4 * 4);
            ((float4*)&Xs[r][0])[c4] = v;
        }
        __syncthreads();

#pragma unroll
        for (int k = 0; k < 64; k += 4) {
            float2 wv[4];
#pragma unroll
            for (int kk = 0; kk < 4; kk++)
                wv[kk] = *(const float2*)&Ws[k + kk][tx * 2];
#pragma unroll
            for (int r = 0; r < 8; r++) {
                float4 xv = *(const float4*)&Xs[ty * 8 + r][k];
                acc[r][0] += xv.x * wv[0].x + xv.y * wv[1].x + xv.z * wv[2].x + xv.w * wv[3].x;
                acc[r][1] += xv.x * wv[0].y + xv.y * wv[1].y + xv.z * wv[2].y + xv.w * wv[3].y;
            }
        }
    }

    float2 bb = *(const float2*)&bias[tx * 2];
#pragma unroll
    for (int r = 0; r < 8; r++) {
        int gr = row0 + ty * 8 + r;
        if (gr < N) {
            float2 o;
            o.x = acc[r][0] + bb.x;
            o.y = acc[r][1] + bb.y;
            *(float2*)(out + (size_t)gr * 64 + tx * 2) = o;
        }
    }
}

// ---------------- launch ----------------
extern "C" void kernel_launch(void* const* d_in, const int* in_sizes, int n_in,
                              void* d_out, int out_size)
{
    const float* x    = (const float*)d_in[0];
    const int*   ei   = (const int*)d_in[1];      // int32 (JAX x64 disabled)
    const float* W1   = (const float*)d_in[2];
    const float* b1   = (const float*)d_in[3];
    const float* W2   = (const float*)d_in[4];
    const float* b2   = (const float*)d_in[5];
    const float* W3   = (const float*)d_in[6];
    const float* b3   = (const float*)d_in[7];
    const float* Wlin = (const float*)d_in[8];
    const float* blin = (const float*)d_in[9];
    float* out = (float*)d_out;

    float *dinv, *csr_w, *hW, *cat;
    int *deg, *rowptr, *cursor, *bsums, *csr_src;
    cudaGetSymbolAddress((void**)&dinv,    g_dinv);
    cudaGetSymbolAddress((void**)&deg,     g_deg);
    cudaGetSymbolAddress((void**)&rowptr,  g_rowptr);
    cudaGetSymbolAddress((void**)&cursor,  g_cursor);
    cudaGetSymbolAddress((void**)&bsums,   g_bsums);
    cudaGetSymbolAddress((void**)&csr_src, g_csr_src);
    cudaGetSymbolAddress((void**)&csr_w,   g_csr_w);
    cudaGetSymbolAddress((void**)&hW,      g_hW);
    cudaGetSymbolAddress((void**)&cat,     g_cat);

    const int N = in_sizes[0] / H;      // 100000
    const int E = in_sizes[1] / 2;      // 1600000
    const int NB = (N + SCAN_CHUNK - 1) / SCAN_CHUNK;   // 196

    const int T = 256;
    const int gN    = (N + T - 1) / T;
    const int gE    = (E + T - 1) / T;
    const int gGemm = (N + 63) / 64;
    const int gAgg  = (N + 7) / 8;

    // CSR build (once; reused by all 3 layers)
    k_zero_deg<<<gN, T>>>(deg, N);
    k_hist   <<<gE, T>>>(deg, ei, E);
    k_dinv   <<<gN, T>>>(dinv, deg, N);
    k_scan1  <<<NB, SCAN_CHUNK>>>(deg, bsums, N);
    k_scan2  <<<1, NB_MAX>>>(bsums, rowptr, NB, N);
    k_scan3  <<<NB, SCAN_CHUNK>>>(deg, bsums, rowptr, cursor, N);
    k_fill   <<<gE, T>>>(ei, dinv, cursor, csr_src, csr_w, E);

    // layer 1: input = x (ld 128)
    k_conv_gemm<<<gGemm, T>>>(x, H, W1, hW, N);
    k_aggregate<<<gAgg, T>>>(rowptr, csr_src, csr_w, dinv, hW, b1, cat, 0, N);

    // layer 2: input = cat slice 0 (ld 384)
    k_conv_gemm<<<gGemm, T>>>(cat, 384, W2, hW, N);
    k_aggregate<<<gAgg, T>>>(rowptr, csr_src, csr_w, dinv, hW, b2, cat, 32, N);

    // layer 3: input = cat slice 1 (ld 384)
    k_conv_gemm<<<gGemm, T>>>(cat + H, 384, W3, hW, N);
    k_aggregate<<<gAgg, T>>>(rowptr, csr_src, csr_w, dinv, hW, b3, cat, 64, N);

    // final: out = cat @ Wlin + blin
    k_final_gemm<<<gGemm, T>>>(cat, Wlin, blin, out, N);
}

// round 6
// speedup vs baseline: 2.9490x; 1.0098x over previous
#include <cuda_runtime.h>

// ---------------- problem constants ----------------
#define NMAX 100000
#define EMAX 1600000
#define H    128
#define SCAN_CHUNK 512
#define NB_MAX 256   // >= ceil(NMAX/SCAN_CHUNK) = 196

// ---------------- device scratch (no allocs allowed) ----------------
__device__ float g_dinv[NMAX];
__device__ int   g_deg[NMAX];
__device__ int   g_rowptr[NMAX + 1];
__device__ int   g_cursor[NMAX];
__device__ int   g_bsums[NB_MAX];
__device__ int   g_csr_src[EMAX];
__device__ float g_csr_w[EMAX];
__device__ float g_hW [(size_t)NMAX * H];
__device__ float g_cat[(size_t)NMAX * 3 * H];   // ld = 384

// ---------------- CSR build ----------------
__global__ void k_zero_deg(int* __restrict__ deg, int N) {
    int i = blockIdx.x * blockDim.x + threadIdx.x;
    if (i < N) deg[i] = 0;
}

__global__ void k_hist(int* __restrict__ deg, const int* __restrict__ ei, int E) {
    int e = blockIdx.x * blockDim.x + threadIdx.x;
    if (e < E) atomicAdd(&deg[ei[E + e]], 1);
}

__global__ void k_dinv(float* __restrict__ dinv, const int* __restrict__ deg, int N) {
    int i = blockIdx.x * blockDim.x + threadIdx.x;
    if (i < N) dinv[i] = rsqrtf(1.0f + (float)deg[i]);
}

__global__ void __launch_bounds__(SCAN_CHUNK) k_scan1(
    const int* __restrict__ deg, int* __restrict__ bsums, int N)
{
    __shared__ int s[SCAN_CHUNK];
    int t = threadIdx.x;
    int i = blockIdx.x * SCAN_CHUNK + t;
    s[t] = (i < N) ? deg[i] : 0;
    __syncthreads();
    for (int off = SCAN_CHUNK / 2; off > 0; off >>= 1) {
        if (t < off) s[t] += s[t + off];
        __syncthreads();
    }
    if (t == 0) bsums[blockIdx.x] = s[0];
}

__global__ void __launch_bounds__(NB_MAX) k_scan2(
    int* __restrict__ bsums, int* __restrict__ rowptr, int NB, int N)
{
    __shared__ int s[NB_MAX];
    int t = threadIdx.x;
    int v = (t < NB) ? bsums[t] : 0;
    s[t] = v;
    __syncthreads();
    for (int off = 1; off < NB_MAX; off <<= 1) {
        int x = (t >= off) ? s[t - off] : 0;
        __syncthreads();
        s[t] += x;
        __syncthreads();
    }
    if (t < NB) bsums[t] = s[t] - v;
    if (t == NB_MAX - 1) rowptr[N] = s[NB_MAX - 1];
}

__global__ void __launch_bounds__(SCAN_CHUNK) k_scan3(
    const int* __restrict__ deg, const int* __restrict__ bsums,
    int* __restrict__ rowptr, int* __restrict__ cursor, int N)
{
    __shared__ int s[SCAN_CHUNK];
    int t = threadIdx.x;
    int i = blockIdx.x * SCAN_CHUNK + t;
    int v = (i < N) ? deg[i] : 0;
    s[t] = v;
    __syncthreads();
    for (int off = 1; off < SCAN_CHUNK; off <<= 1) {
        int x = (t >= off) ? s[t - off] : 0;
        __syncthreads();
        s[t] += x;
        __syncthreads();
    }
    if (i < N) {
        int excl = s[t] - v + bsums[blockIdx.x];
        rowptr[i] = excl;
        cursor[i] = excl;
    }
}

__global__ void k_fill(const int* __restrict__ ei,
                       const float* __restrict__ dinv,
                       int* __restrict__ cursor,
                       int* __restrict__ csr_src,
                       float* __restrict__ csr_w, int E)
{
    int e = blockIdx.x * blockDim.x + threadIdx.x;
    if (e >= E) return;
    int r = ei[e];
    int c = ei[E + e];
    int pos = atomicAdd(&cursor[c], 1);
    csr_src[pos] = r;
    csr_w[pos]   = dinv[r];
}

// ---------------- conv GEMM: hW = X @ W ----------------
// 128x128 block tile, 256 threads, 8x8 per thread, k-chunk 32.
// Xs stored k-major, pad 132 (16B-aligned rows; 4-way STS conflict only).
__global__ void __launch_bounds__(256) k_conv_gemm(
    const float* __restrict__ X, int ldx,
    const float* __restrict__ W,
    float* __restrict__ hW, int N)
{
    __shared__ float Xs[32][132];   // [k][row], row stride 528B (16B-aligned)
    __shared__ float Ws[32][128];   // [k][col]

    const int tid  = threadIdx.x;
    const int row0 = blockIdx.x * 128;
    const int tx   = tid & 15;      // cols tx*8 .. +8
    const int ty   = tid >> 4;      // rows ty*8 .. +8

    float acc[8][8];
#pragma unroll
    for (int r = 0; r < 8; r++)
#pragma unroll
        for (int c = 0; c < 8; c++) acc[r][c] = 0.f;

    for (int kc = 0; kc < 128; kc += 32) {
        __syncthreads();
        // W chunk: rows [kc,kc+32) of W[128][128]; 1024 float4
#pragma unroll
        for (int i = tid; i < 1024; i += 256) {
            int k = i >> 5, c4 = i & 31;
            ((float4*)&Ws[k][0])[c4] =
                ((const float4*)(W + (size_t)(kc + k) * 128))[c4];
        }
        // X chunk transposed: 128 rows x 32 k
#pragma unroll
        for (int i = tid; i < 1024; i += 256) {
            int r = i >> 3, c4 = i & 7;
            int gr = row0 + r;
            float4 v = make_float4(0.f, 0.f, 0.f, 0.f);
            if (gr < N) v = *(const float4*)(X + (size_t)gr * ldx + kc + c4 * 4);
            Xs[c4 * 4 + 0][r] = v.x;
            Xs[c4 * 4 + 1][r] = v.y;
            Xs[c4 * 4 + 2][r] = v.z;
            Xs[c4 * 4 + 3][r] = v.w;
        }
        __syncthreads();

#pragma unroll 4
        for (int k = 0; k < 32; k++) {
            float a[8], b[8];
            *(float4*)&a[0] = *(const float4*)&Xs[k][ty * 8];
            *(float4*)&a[4] = *(const float4*)&Xs[k][ty * 8 + 4];
            *(float4*)&b[0] = *(const float4*)&Ws[k][tx * 8];
            *(float4*)&b[4] = *(const float4*)&Ws[k][tx * 8 + 4];
#pragma unroll
            for (int r = 0; r < 8; r++)
#pragma unroll
                for (int c = 0; c < 8; c++)
                    acc[r][c] += a[r] * b[c];
        }
    }

#pragma unroll
    for (int r = 0; r < 8; r++) {
        int gr = row0 + ty * 8 + r;
        if (gr < N) {
            *(float4*)(hW + (size_t)gr * H + tx * 8)     =
                make_float4(acc[r][0], acc[r][1], acc[r][2], acc[r][3]);
            *(float4*)(hW + (size_t)gr * H + tx * 8 + 4) =
                make_float4(acc[r][4], acc[r][5], acc[r][6], acc[r][7]);
        }
    }
}

// ---------------- fused aggregate + self-loop + bias + relu -> cat slice ----------------
__global__ void __launch_bounds__(256) k_aggregate(
    const int* __restrict__ rowptr,
    const int* __restrict__ csr_src,
    const float* __restrict__ csr_w,
    const float* __restrict__ dinv,
    const float* __restrict__ hW,
    const float* __restrict__ bias,
    float* __restrict__ cat, int off4, int N)
{
    int n = blockIdx.x * 8 + (threadIdx.x >> 5);
    if (n >= N) return;
    int lane = threadIdx.x & 31;

    float dv = dinv[n];
    float sn = dv * dv;
    float4 self = ((const float4*)(hW + (size_t)n * H))[lane];
    float4 acc = make_float4(self.x * sn, self.y * sn, self.z * sn, self.w * sn);

    int beg = rowptr[n], end = rowptr[n + 1];
    int i = beg;
    for (; i + 4 <= end; i += 4) {
        int   r0 = csr_src[i],   r1 = csr_src[i+1], r2 = csr_src[i+2], r3 = csr_src[i+3];
        float w0 = csr_w[i]*dv,  w1 = csr_w[i+1]*dv, w2 = csr_w[i+2]*dv, w3 = csr_w[i+3]*dv;
        float4 v0 = ((const float4*)(hW + (size_t)r0 * H))[lane];
        float4 v1 = ((const float4*)(hW + (size_t)r1 * H))[lane];
        float4 v2 = ((const float4*)(hW + (size_t)r2 * H))[lane];
        float4 v3 = ((const float4*)(hW + (size_t)r3 * H))[lane];
        acc.x += v0.x*w0 + v1.x*w1 + v2.x*w2 + v3.x*w3;
        acc.y += v0.y*w0 + v1.y*w1 + v2.y*w2 + v3.y*w3;
        acc.z += v0.z*w0 + v1.z*w1 + v2.z*w2 + v3.z*w3;
        acc.w += v0.w*w0 + v1.w*w1 + v2.w*w2 + v3.w*w3;
    }
    for (; i < end; i++) {
        int   r = csr_src[i];
        float w = csr_w[i] * dv;
        float4 v = ((const float4*)(hW + (size_t)r * H))[lane];
        acc.x += v.x * w; acc.y += v.y * w; acc.z += v.z * w; acc.w += v.w * w;
    }

    float4 bb = ((const float4*)bias)[lane];
    acc.x = fmaxf(acc.x + bb.x, 0.f);
    acc.y = fmaxf(acc.y + bb.y, 0.f);
    acc.z = fmaxf(acc.z + bb.z, 0.f);
    acc.w = fmaxf(acc.w + bb.w, 0.f);
    ((float4*)cat)[(size_t)n * 96 + off4 + lane] = acc;
}

// ---------------- final GEMM: out = cat[N,384] @ Wlin[384,64] + blin ----------------
// 128x64 tile, 256 threads, 8x4 per thread, k-chunk 32.
__global__ void __launch_bounds__(256) k_final_gemm(
    const float* __restrict__ cat,
    const float* __restrict__ W,     // [384,64]
    const float* __restrict__ bias,  // [64]
    float* __restrict__ out, int N)
{
    __shared__ float Xs[32][132];   // [k][row], 16B-aligned rows
    __shared__ float Ws[32][64];    // [k][col]

    const int tid  = threadIdx.x;
    const int row0 = blockIdx.x * 128;
    const int tx   = tid & 15;      // cols tx*4 .. +4
    const int ty   = tid >> 4;      // rows ty*8 .. +8

    float acc[8][4];
#pragma unroll
    for (int r = 0; r < 8; r++)
#pragma unroll
        for (int c = 0; c < 4; c++) acc[r][c] = 0.f;

    for (int kc = 0; kc < 384; kc += 32) {
        __syncthreads();
        // W chunk: 32x64 = 512 float4
#pragma unroll
        for (int i = tid; i < 512; i += 256) {
            int k = i >> 4, c4 = i & 15;
            ((float4*)&Ws[k][0])[c4] =
                ((const float4*)(W + (size_t)(kc + k) * 64))[c4];
        }
        // X chunk transposed
#pragma unroll
        for (int i = tid; i < 1024; i += 256) {
            int r = i >> 3, c4 = i & 7;
            int gr = row0 + r;
            float4 v = make_float4(0.f, 0.f, 0.f, 0.f);
            if (gr < N) v = *(const float4*)(cat + (size_t)gr * 384 + kc + c4 * 4);
            Xs[c4 * 4 + 0][r] = v.x;
            Xs[c4 * 4 + 1][r] = v.y;
            Xs[c4 * 4 + 2][r] = v.z;
            Xs[c4 * 4 + 3][r] = v.w;
        }
        __syncthreads();

#pragma unroll 4
        for (int k = 0; k < 32; k++) {
            float a[8], b[4];
            *(float4*)&a[0] = *(const float4*)&Xs[k][ty * 8];
            *(float4*)&a[4] = *(const float4*)&Xs[k][ty * 8 + 4];
            *(float4*)&b[0] = *(const float4*)&Ws[k][tx * 4];
#pragma unroll
            for (int r = 0; r < 8; r++)
#pragma unroll
                for (int c = 0; c < 4; c++)
                    acc[r][c] += a[r] * b[c];
        }
    }

    float4 bb = *(const float4*)&bias[tx * 4];
#pragma unroll
    for (int r = 0; r < 8; r++) {
        int gr = row0 + ty * 8 + r;
        if (gr < N) {
            float4 o;
            o.x = acc[r][0] + bb.x;
            o.y = acc[r][1] + bb.y;
            o.z = acc[r][2] + bb.z;
            o.w = acc[r][3] + bb.w;
            *(float4*)(out + (size_t)gr * 64 + tx * 4) = o;
        }
    }
}

// ---------------- launch ----------------
extern "C" void kernel_launch(void* const* d_in, const int* in_sizes, int n_in,
                              void* d_out, int out_size)
{
    const float* x    = (const float*)d_in[0];
    const int*   ei   = (const int*)d_in[1];      // int32 (JAX x64 disabled)
    const float* W1   = (const float*)d_in[2];
    const float* b1   = (const float*)d_in[3];
    const float* W2   = (const float*)d_in[4];
    const float* b2   = (const float*)d_in[5];
    const float* W3   = (const float*)d_in[6];
    const float* b3   = (const float*)d_in[7];
    const float* Wlin = (const float*)d_in[8];
    const float* blin = (const float*)d_in[9];
    float* out = (float*)d_out;

    float *dinv, *csr_w, *hW, *cat;
    int *deg, *rowptr, *cursor, *bsums, *csr_src;
    cudaGetSymbolAddress((void**)&dinv,    g_dinv);
    cudaGetSymbolAddress((void**)&deg,     g_deg);
    cudaGetSymbolAddress((void**)&rowptr,  g_rowptr);
    cudaGetSymbolAddress((void**)&cursor,  g_cursor);
    cudaGetSymbolAddress((void**)&bsums,   g_bsums);
    cudaGetSymbolAddress((void**)&csr_src, g_csr_src);
    cudaGetSymbolAddress((void**)&csr_w,   g_csr_w);
    cudaGetSymbolAddress((void**)&hW,      g_hW);
    cudaGetSymbolAddress((void**)&cat,     g_cat);

    const int N = in_sizes[0] / H;      // 100000
    const int E = in_sizes[1] / 2;      // 1600000
    const int NB = (N + SCAN_CHUNK - 1) / SCAN_CHUNK;

    const int T = 256;
    const int gN    = (N + T - 1) / T;
    const int gE    = (E + T - 1) / T;
    const int gGemm = (N + 127) / 128;
    const int gAgg  = (N + 7) / 8;

    // layer-1 GEMM first (independent of CSR build)
    k_conv_gemm<<<gGemm, T>>>(x, H, W1, hW, N);

    // CSR build (once; reused by all 3 layers)
    k_zero_deg<<<gN, T>>>(deg, N);
    k_hist   <<<gE, T>>>(deg, ei, E);
    k_dinv   <<<gN, T>>>(dinv, deg, N);
    k_scan1  <<<NB, SCAN_CHUNK>>>(deg, bsums, N);
    k_scan2  <<<1, NB_MAX>>>(bsums, rowptr, NB, N);
    k_scan3  <<<NB, SCAN_CHUNK>>>(deg, bsums, rowptr, cursor, N);
    k_fill   <<<gE, T>>>(ei, dinv, cursor, csr_src, csr_w, E);

    // layer 1 aggregate
    k_aggregate<<<gAgg, T>>>(rowptr, csr_src, csr_w, dinv, hW, b1, cat, 0, N);

    // layer 2
    k_conv_gemm<<<gGemm, T>>>(cat, 384, W2, hW, N);
    k_aggregate<<<gAgg, T>>>(rowptr, csr_src, csr_w, dinv, hW, b2, cat, 32, N);

    // layer 3
    k_conv_gemm<<<gGemm, T>>>(cat + H, 384, W3, hW, N);
    k_aggregate<<<gAgg, T>>>(rowptr, csr_src, csr_w, dinv, hW, b3, cat, 64, N);

    // final
    k_final_gemm<<<gGemm, T>>>(cat, Wlin, blin, out, N);
}

// round 7
// speedup vs baseline: 4.3127x; 1.4624x over previous
#include <cuda_runtime.h>
#include <cstdint>

// ---------------- problem constants ----------------
#define NMAX 100000
#define EMAX 1600000
#define H    128
#define SCAN_CHUNK 512
#define NB_MAX 256

// ---------------- device scratch (no allocs allowed) ----------------
__device__ float g_dinv[NMAX];
__device__ int   g_deg[NMAX];
__device__ int   g_rowptr[NMAX + 1];
__device__ int   g_cursor[NMAX];
__device__ int   g_bsums[NB_MAX];
__device__ int   g_csr_src[EMAX];
__device__ float g_csr_w[EMAX];
__device__ float g_hW [(size_t)NMAX * H];
__device__ float g_cat[(size_t)NMAX * 3 * H];   // ld = 384

// ---------------- tf32 helpers ----------------
__device__ __forceinline__ uint32_t f2tf32(float f) {
    uint32_t u;
    asm("cvt.rna.tf32.f32 %0, %1;" : "=r"(u) : "f"(f));
    return u;
}

__device__ __forceinline__ void mma_tf32(float* d, const uint32_t* a, const uint32_t* b) {
    asm volatile(
        "mma.sync.aligned.m16n8k8.row.col.f32.tf32.tf32.f32 "
        "{%0,%1,%2,%3}, {%4,%5,%6,%7}, {%8,%9}, {%0,%1,%2,%3};"
        : "+f"(d[0]), "+f"(d[1]), "+f"(d[2]), "+f"(d[3])
        : "r"(a[0]), "r"(a[1]), "r"(a[2]), "r"(a[3]), "r"(b[0]), "r"(b[1]));
}

// ---------------- CSR build ----------------
__global__ void k_zero_deg(int* __restrict__ deg, int N) {
    int i = blockIdx.x * blockDim.x + threadIdx.x;
    if (i < N) deg[i] = 0;
}

__global__ void k_hist(int* __restrict__ deg, const int* __restrict__ ei, int E) {
    int e = blockIdx.x * blockDim.x + threadIdx.x;
    if (e < E) atomicAdd(&deg[ei[E + e]], 1);
}

__global__ void k_dinv(float* __restrict__ dinv, const int* __restrict__ deg, int N) {
    int i = blockIdx.x * blockDim.x + threadIdx.x;
    if (i < N) dinv[i] = rsqrtf(1.0f + (float)deg[i]);
}

__global__ void __launch_bounds__(SCAN_CHUNK) k_scan1(
    const int* __restrict__ deg, int* __restrict__ bsums, int N)
{
    __shared__ int s[SCAN_CHUNK];
    int t = threadIdx.x;
    int i = blockIdx.x * SCAN_CHUNK + t;
    s[t] = (i < N) ? deg[i] : 0;
    __syncthreads();
    for (int off = SCAN_CHUNK / 2; off > 0; off >>= 1) {
        if (t < off) s[t] += s[t + off];
        __syncthreads();
    }
    if (t == 0) bsums[blockIdx.x] = s[0];
}

__global__ void __launch_bounds__(NB_MAX) k_scan2(
    int* __restrict__ bsums, int* __restrict__ rowptr, int NB, int N)
{
    __shared__ int s[NB_MAX];
    int t = threadIdx.x;
    int v = (t < NB) ? bsums[t] : 0;
    s[t] = v;
    __syncthreads();
    for (int off = 1; off < NB_MAX; off <<= 1) {
        int x = (t >= off) ? s[t - off] : 0;
        __syncthreads();
        s[t] += x;
        __syncthreads();
    }
    if (t < NB) bsums[t] = s[t] - v;
    if (t == NB_MAX - 1) rowptr[N] = s[NB_MAX - 1];
}

__global__ void __launch_bounds__(SCAN_CHUNK) k_scan3(
    const int* __restrict__ deg, const int* __restrict__ bsums,
    int* __restrict__ rowptr, int* __restrict__ cursor, int N)
{
    __shared__ int s[SCAN_CHUNK];
    int t = threadIdx.x;
    int i = blockIdx.x * SCAN_CHUNK + t;
    int v = (i < N) ? deg[i] : 0;
    s[t] = v;
    __syncthreads();
    for (int off = 1; off < SCAN_CHUNK; off <<= 1) {
        int x = (t >= off) ? s[t - off] : 0;
        __syncthreads();
        s[t] += x;
        __syncthreads();
    }
    if (i < N) {
        int excl = s[t] - v + bsums[blockIdx.x];
        rowptr[i] = excl;
        cursor[i] = excl;
    }
}

__global__ void k_fill(const int* __restrict__ ei,
                       const float* __restrict__ dinv,
                       int* __restrict__ cursor,
                       int* __restrict__ csr_src,
                       float* __restrict__ csr_w, int E)
{
    int e = blockIdx.x * blockDim.x + threadIdx.x;
    if (e >= E) return;
    int r = ei[e];
    int c = ei[E + e];
    int pos = atomicAdd(&cursor[c], 1);
    csr_src[pos] = r;
    csr_w[pos]   = dinv[r];
}

// ---------------- conv GEMM (tf32 tensor core): hW = X @ W ----------------
// Block tile 128x128, 8 warps (2x4), warp tile 64x32, K chunks of 32.
// Xs: k-major [32][132] tf32, Ws: k-major [32][136] tf32 (stride%32==8 -> B-frag conflict-free).
__global__ void __launch_bounds__(256) k_conv_gemm(
    const float* __restrict__ X, int ldx,
    const float* __restrict__ W,
    float* __restrict__ hW, int N)
{
    __shared__ uint32_t Xs[32][132];
    __shared__ uint32_t Ws[32][136];

    const int tid  = threadIdx.x;
    const int lane = tid & 31;
    const int warp = tid >> 5;
    const int wm   = warp >> 2;         // 0..1 -> row block of 64
    const int wn   = warp & 3;          // 0..3 -> col block of 32
    const int row0 = blockIdx.x * 128;

    const int g  = lane >> 2;           // group id 0..7
    const int tg = lane & 3;            // thread-in-group 0..3

    float acc[4][4][4];
#pragma unroll
    for (int i = 0; i < 4; i++)
#pragma unroll
        for (int j = 0; j < 4; j++)
#pragma unroll
            for (int q = 0; q < 4; q++) acc[i][j][q] = 0.f;

    for (int kc = 0; kc < 128; kc += 32) {
        __syncthreads();
        // W chunk rows [kc,kc+32): 32x128 -> Ws[k][col], tf32, vector STS
#pragma unroll
        for (int i = tid; i < 1024; i += 256) {
            int k = i >> 5, c4 = i & 31;
            float4 v = ((const float4*)(W + (size_t)(kc + k) * 128))[c4];
            uint4 t = make_uint4(f2tf32(v.x), f2tf32(v.y), f2tf32(v.z), f2tf32(v.w));
            *(uint4*)&Ws[k][c4 * 4] = t;
        }
        // X chunk transposed: rows [row0,row0+128) x k [kc,kc+32) -> Xs[k][row]
#pragma unroll
        for (int i = tid; i < 1024; i += 256) {
            int r = i >> 3, c4 = i & 7;
            int gr = row0 + r;
            float4 v = make_float4(0.f, 0.f, 0.f, 0.f);
            if (gr < N) v = *(const float4*)(X + (size_t)gr * ldx + kc + c4 * 4);
            Xs[c4 * 4 + 0][r] = f2tf32(v.x);
            Xs[c4 * 4 + 1][r] = f2tf32(v.y);
            Xs[c4 * 4 + 2][r] = f2tf32(v.z);
            Xs[c4 * 4 + 3][r] = f2tf32(v.w);
        }
        __syncthreads();

#pragma unroll
        for (int kk = 0; kk < 4; kk++) {
            const int kb = kk * 8;
            uint32_t a[4][4], b[4][2];
#pragma unroll
            for (int i = 0; i < 4; i++) {
                int r = wm * 64 + i * 16 + g;
                a[i][0] = Xs[kb + tg    ][r];
                a[i][1] = Xs[kb + tg    ][r + 8];
                a[i][2] = Xs[kb + tg + 4][r];
                a[i][3] = Xs[kb + tg + 4][r + 8];
            }
#pragma unroll
            for (int j = 0; j < 4; j++) {
                int cb = wn * 32 + j * 8 + g;
                b[j][0] = Ws[kb + tg    ][cb];
                b[j][1] = Ws[kb + tg + 4][cb];
            }
#pragma unroll
            for (int i = 0; i < 4; i++)
#pragma unroll
                for (int j = 0; j < 4; j++)
                    mma_tf32(acc[i][j], a[i], b[j]);
        }
    }

    // epilogue: d0,d1 -> (row, 2tg), (row, 2tg+1); d2,d3 -> row+8
#pragma unroll
    for (int i = 0; i < 4; i++) {
        int r = row0 + wm * 64 + i * 16 + g;
#pragma unroll
        for (int j = 0; j < 4; j++) {
            int c = wn * 32 + j * 8 + 2 * tg;
            if (r < N)
                *(float2*)(hW + (size_t)r * H + c) = make_float2(acc[i][j][0], acc[i][j][1]);
            if (r + 8 < N)
                *(float2*)(hW + (size_t)(r + 8) * H + c) = make_float2(acc[i][j][2], acc[i][j][3]);
        }
    }
}

// ---------------- fused aggregate + self-loop + bias + relu -> cat slice ----------------
__global__ void __launch_bounds__(256) k_aggregate(
    const int* __restrict__ rowptr,
    const int* __restrict__ csr_src,
    const float* __restrict__ csr_w,
    const float* __restrict__ dinv,
    const float* __restrict__ hW,
    const float* __restrict__ bias,
    float* __restrict__ cat, int off4, int N)
{
    int n = blockIdx.x * 8 + (threadIdx.x >> 5);
    if (n >= N) return;
    int lane = threadIdx.x & 31;

    float dv = dinv[n];
    float sn = dv * dv;
    float4 self = ((const float4*)(hW + (size_t)n * H))[lane];
    float4 acc = make_float4(self.x * sn, self.y * sn, self.z * sn, self.w * sn);

    int beg = rowptr[n], end = rowptr[n + 1];
    int i = beg;
    for (; i + 4 <= end; i += 4) {
        int   r0 = csr_src[i],   r1 = csr_src[i+1], r2 = csr_src[i+2], r3 = csr_src[i+3];
        float w0 = csr_w[i]*dv,  w1 = csr_w[i+1]*dv, w2 = csr_w[i+2]*dv, w3 = csr_w[i+3]*dv;
        float4 v0 = ((const float4*)(hW + (size_t)r0 * H))[lane];
        float4 v1 = ((const float4*)(hW + (size_t)r1 * H))[lane];
        float4 v2 = ((const float4*)(hW + (size_t)r2 * H))[lane];
        float4 v3 = ((const float4*)(hW + (size_t)r3 * H))[lane];
        acc.x += v0.x*w0 + v1.x*w1 + v2.x*w2 + v3.x*w3;
        acc.y += v0.y*w0 + v1.y*w1 + v2.y*w2 + v3.y*w3;
        acc.z += v0.z*w0 + v1.z*w1 + v2.z*w2 + v3.z*w3;
        acc.w += v0.w*w0 + v1.w*w1 + v2.w*w2 + v3.w*w3;
    }
    for (; i < end; i++) {
        int   r = csr_src[i];
        float w = csr_w[i] * dv;
        float4 v = ((const float4*)(hW + (size_t)r * H))[lane];
        acc.x += v.x * w; acc.y += v.y * w; acc.z += v.z * w; acc.w += v.w * w;
    }

    float4 bb = ((const float4*)bias)[lane];
    acc.x = fmaxf(acc.x + bb.x, 0.f);
    acc.y = fmaxf(acc.y + bb.y, 0.f);
    acc.z = fmaxf(acc.z + bb.z, 0.f);
    acc.w = fmaxf(acc.w + bb.w, 0.f);
    ((float4*)cat)[(size_t)n * 96 + off4 + lane] = acc;
}

// ---------------- final GEMM (tf32): out = cat[N,384] @ Wlin[384,64] + blin ----------------
// Block tile 128x64, 8 warps (4x2), warp tile 32x32, K chunks of 32.
__global__ void __launch_bounds__(256) k_final_gemm(
    const float* __restrict__ cat,
    const float* __restrict__ W,     // [384,64]
    const float* __restrict__ bias,  // [64]
    float* __restrict__ out, int N)
{
    __shared__ uint32_t Xs[32][132];
    __shared__ uint32_t Ws[32][72];   // stride%32==8 -> conflict-free B-frag loads

    const int tid  = threadIdx.x;
    const int lane = tid & 31;
    const int warp = tid >> 5;
    const int wm   = warp & 3;          // 0..3 -> row block of 32
    const int wn   = warp >> 2;         // 0..1 -> col block of 32
    const int row0 = blockIdx.x * 128;

    const int g  = lane >> 2;
    const int tg = lane & 3;

    float acc[2][4][4];
#pragma unroll
    for (int i = 0; i < 2; i++)
#pragma unroll
        for (int j = 0; j < 4; j++)
#pragma unroll
            for (int q = 0; q < 4; q++) acc[i][j][q] = 0.f;

    for (int kc = 0; kc < 384; kc += 32) {
        __syncthreads();
        // W chunk: 32x64 -> Ws[k][col]
#pragma unroll
        for (int i = tid; i < 512; i += 256) {
            int k = i >> 4, c4 = i & 15;
            float4 v = ((const float4*)(W + (size_t)(kc + k) * 64))[c4];
            uint4 t = make_uint4(f2tf32(v.x), f2tf32(v.y), f2tf32(v.z), f2tf32(v.w));
            *(uint4*)&Ws[k][c4 * 4] = t;
        }
        // X chunk transposed
#pragma unroll
        for (int i = tid; i < 1024; i += 256) {
            int r = i >> 3, c4 = i & 7;
            int gr = row0 + r;
            float4 v = make_float4(0.f, 0.f, 0.f, 0.f);
            if (gr < N) v = *(const float4*)(cat + (size_t)gr * 384 + kc + c4 * 4);
            Xs[c4 * 4 + 0][r] = f2tf32(v.x);
            Xs[c4 * 4 + 1][r] = f2tf32(v.y);
            Xs[c4 * 4 + 2][r] = f2tf32(v.z);
            Xs[c4 * 4 + 3][r] = f2tf32(v.w);
        }
        __syncthreads();

#pragma unroll
        for (int kk = 0; kk < 4; kk++) {
            const int kb = kk * 8;
            uint32_t a[2][4], b[4][2];
#pragma unroll
            for (int i = 0; i < 2; i++) {
                int r = wm * 32 + i * 16 + g;
                a[i][0] = Xs[kb + tg    ][r];
                a[i][1] = Xs[kb + tg    ][r + 8];
                a[i][2] = Xs[kb + tg + 4][r];
                a[i][3] = Xs[kb + tg + 4][r + 8];
            }
#pragma unroll
            for (int j = 0; j < 4; j++) {
                int cb = wn * 32 + j * 8 + g;
                b[j][0] = Ws[kb + tg    ][cb];
                b[j][1] = Ws[kb + tg + 4][cb];
            }
#pragma unroll
            for (int i = 0; i < 2; i++)
#pragma unroll
                for (int j = 0; j < 4; j++)
                    mma_tf32(acc[i][j], a[i], b[j]);
        }
    }

#pragma unroll
    for (int i = 0; i < 2; i++) {
        int r = row0 + wm * 32 + i * 16 + g;
#pragma unroll
        for (int j = 0; j < 4; j++) {
            int c = wn * 32 + j * 8 + 2 * tg;
            float b0 = bias[c], b1 = bias[c + 1];
            if (r < N)
                *(float2*)(out + (size_t)r * 64 + c) =
                    make_float2(acc[i][j][0] + b0, acc[i][j][1] + b1);
            if (r + 8 < N)
                *(float2*)(out + (size_t)(r + 8) * 64 + c) =
                    make_float2(acc[i][j][2] + b0, acc[i][j][3] + b1);
        }
    }
}

// ---------------- launch ----------------
extern "C" void kernel_launch(void* const* d_in, const int* in_sizes, int n_in,
                              void* d_out, int out_size)
{
    const float* x    = (const float*)d_in[0];
    const int*   ei   = (const int*)d_in[1];      // int32 (JAX x64 disabled)
    const float* W1   = (const float*)d_in[2];
    const float* b1   = (const float*)d_in[3];
    const float* W2   = (const float*)d_in[4];
    const float* b2   = (const float*)d_in[5];
    const float* W3   = (const float*)d_in[6];
    const float* b3   = (const float*)d_in[7];
    const float* Wlin = (const float*)d_in[8];
    const float* blin = (const float*)d_in[9];
    float* out = (float*)d_out;

    float *dinv, *csr_w, *hW, *cat;
    int *deg, *rowptr, *cursor, *bsums, *csr_src;
    cudaGetSymbolAddress((void**)&dinv,    g_dinv);
    cudaGetSymbolAddress((void**)&deg,     g_deg);
    cudaGetSymbolAddress((void**)&rowptr,  g_rowptr);
    cudaGetSymbolAddress((void**)&cursor,  g_cursor);
    cudaGetSymbolAddress((void**)&bsums,   g_bsums);
    cudaGetSymbolAddress((void**)&csr_src, g_csr_src);
    cudaGetSymbolAddress((void**)&csr_w,   g_csr_w);
    cudaGetSymbolAddress((void**)&hW,      g_hW);
    cudaGetSymbolAddress((void**)&cat,     g_cat);

    const int N = in_sizes[0] / H;      // 100000
    const int E = in_sizes[1] / 2;      // 1600000
    const int NB = (N + SCAN_CHUNK - 1) / SCAN_CHUNK;

    const int T = 256;
    const int gN    = (N + T - 1) / T;
    const int gE    = (E + T - 1) / T;
    const int gGemm = (N + 127) / 128;
    const int gAgg  = (N + 7) / 8;

    // layer-1 GEMM first (independent of CSR build)
    k_conv_gemm<<<gGemm, T>>>(x, H, W1, hW, N);

    // CSR build (once; reused by all 3 layers)
    k_zero_deg<<<gN, T>>>(deg, N);
    k_hist   <<<gE, T>>>(deg, ei, E);
    k_dinv   <<<gN, T>>>(dinv, deg, N);
    k_scan1  <<<NB, SCAN_CHUNK>>>(deg, bsums, N);
    k_scan2  <<<1, NB_MAX>>>(bsums, rowptr, NB, N);
    k_scan3  <<<NB, SCAN_CHUNK>>>(deg, bsums, rowptr, cursor, N);
    k_fill   <<<gE, T>>>(ei, dinv, cursor, csr_src, csr_w, E);

    // layer 1 aggregate
    k_aggregate<<<gAgg, T>>>(rowptr, csr_src, csr_w, dinv, hW, b1, cat, 0, N);

    // layer 2
    k_conv_gemm<<<gGemm, T>>>(cat, 384, W2, hW, N);
    k_aggregate<<<gAgg, T>>>(rowptr, csr_src, csr_w, dinv, hW, b2, cat, 32, N);

    // layer 3
    k_conv_gemm<<<gGemm, T>>>(cat + H, 384, W3, hW, N);
    k_aggregate<<<gAgg, T>>>(rowptr, csr_src, csr_w, dinv, hW, b3, cat, 64, N);

    // final
    k_final_gemm<<<gGemm, T>>>(cat, Wlin, blin, out, N);
}